// round 8
// baseline (speedup 1.0000x reference)
#include <cuda_runtime.h>
#include <cuda_bf16.h>
#include <cstdint>
#include <cstddef>

#define HD        2048
#define SEQ       8192
#define IN_DIM    16
#define NCTA      147
#define JCAP      14
#define WARPS     7
#define TPB       (WARPS * 32)        // 224 threads
#define SCH       12                  // smem bf16 weight chunks (cols 0..1535)
#define RCH       4                   // reg fp32 weight chunks (cols 1536..2047)
#define SMEM_W_COLS (SCH * 128)       // 1536
#define W_ROW_B   (SMEM_W_COLS * 2)   // 3072 bytes per bf16 weight row
#define SMEM_BYTES (HD * 4 + 56 * W_ROW_B)   // 8192 + 172032 = 180224

// Persistent scratch (static __device__ globals — no allocation APIs).
__device__ float d_hs[(size_t)(SEQ + 1) * HD];  // h history, row 0 == h_0 == 0
__device__ int   d_cnt;                         // global arrival counter

__device__ __forceinline__ int ld_acq(const int* p) {
    int v;
    asm volatile("ld.acquire.gpu.global.b32 %0, [%1];" : "=r"(v) : "l"(p));
    return v;
}
__device__ __forceinline__ void red_rel_add(int* p, int v) {
    asm volatile("red.release.gpu.global.add.s32 [%0], %1;" :: "l"(p), "r"(v) : "memory");
}

__device__ __forceinline__ float sigmoidf_(float x) {
    return 1.0f / (1.0f + __expf(-x));
}
__device__ __forceinline__ float tanh_fast(float x) {
    float xc = fminf(fmaxf(x, -15.0f), 15.0f);   // keep __expf finite
    float a = __expf(2.0f * xc);
    return (a - 1.0f) / (a + 1.0f);
}

// Packed f32x2 FMA: acc(2xf32) += unpack_bf16x2(u) * h2(2xf32)
// u holds bf16 col c0 in low half, c1 in high half.
// low f32 = u<<16 (c0), high f32 = u & 0xffff0000 (c1) — matches h pair order.
__device__ __forceinline__ void ffma2_bf(unsigned long long& acc, unsigned u,
                                         unsigned long long h2) {
    unsigned long long wpk;
    asm("{\n\t"
        ".reg .b32 lo, hi;\n\t"
        "shl.b32 lo, %1, 16;\n\t"
        "and.b32 hi, %1, 0xffff0000;\n\t"
        "mov.b64 %0, {lo, hi};\n\t"
        "}" : "=l"(wpk) : "r"(u));
    asm("fma.rn.f32x2 %0, %1, %2, %0;" : "+l"(acc) : "l"(wpk), "l"(h2));
}
// Packed f32x2 FMA with pre-packed fp32 weight pair.
__device__ __forceinline__ void ffma2_f(unsigned long long& acc,
                                        unsigned long long wpk,
                                        unsigned long long h2) {
    asm("fma.rn.f32x2 %0, %1, %2, %0;" : "+l"(acc) : "l"(wpk), "l"(h2));
}
__device__ __forceinline__ unsigned long long pack2f(float a, float b) {
    return (unsigned long long)__float_as_uint(a) |
           ((unsigned long long)__float_as_uint(b) << 32);
}

// ---------------------------------------------------------------------------
// Persistent LSTM. CTA b owns hidden units [b*14, b*14+J). 7 warps, 8 gate
// rows each (= 2 units: w and w+7). Weights: cols [0,1536) bf16 in SMEM,
// cols [1536,2048) exact fp32 packed pairs in registers. All MACs via
// fma.rn.f32x2. Grid barrier: one release-RED per CTA into d_cnt, one
// poller thread acquires.
// ---------------------------------------------------------------------------
extern "C" __global__ void __launch_bounds__(TPB, 1)
lstm_persist(const float* __restrict__ sa,  const float* __restrict__ Wih,
             const float* __restrict__ Whh, const float* __restrict__ bih,
             const float* __restrict__ bhh)
{
    extern __shared__ unsigned char smem[];
    float*         h_sm = (float*)smem;                 // 2048 f32
    unsigned char* wsm  = smem + HD * 4;                // bf16 weights

    const int tid  = threadIdx.x;
    const int w    = tid >> 5;
    const int lane = tid & 31;
    const int b    = blockIdx.x;
    const int j0   = b * JCAP;
    const int J    = (b == NCTA - 1) ? (HD - (NCTA - 1) * JCAP) : JCAP;  // 14 or 4

    // Row set for this warp: i = 0..7 -> gate g = i&3 of unit jj = w + 7*(i>>2).
    int  rl[8], gr[8];
    bool rv[8];
    #pragma unroll
    for (int i = 0; i < 8; ++i) {
        int jj = w + 7 * (i >> 2);
        int g  = i & 3;
        rv[i] = (jj < J);
        int jjc = rv[i] ? jj : 0;
        rl[i] = g * J + jjc;           // local smem row
        gr[i] = g * HD + j0 + jjc;     // global gate row
    }

    // ---- init: stage bf16 weights for cols [0,1536) into SMEM ----
    for (int idx = tid; idx < 4 * J * SMEM_W_COLS; idx += TPB) {
        int r   = idx / SMEM_W_COLS;
        int col = idx - r * SMEM_W_COLS;
        int gg  = r / J, jj = r - gg * J;
        int grow = gg * HD + j0 + jj;
        ((__nv_bfloat16*)wsm)[(size_t)r * SMEM_W_COLS + col] =
            __float2bfloat16(Whh[(size_t)grow * HD + col]);
    }

    // ---- init: fp32 register weights for cols [1536,2048), packed pairs ----
    unsigned long long wf[8][RCH][2];
    #pragma unroll
    for (int i = 0; i < 8; ++i) {
        #pragma unroll
        for (int c = 0; c < RCH; ++c) {
            if (rv[i]) {
                const float* wr = Whh + (size_t)gr[i] * HD + SMEM_W_COLS + 128 * c + 4 * lane;
                wf[i][c][0] = pack2f(wr[0], wr[1]);
                wf[i][c][1] = pack2f(wr[2], wr[3]);
            } else {
                wf[i][c][0] = 0ull; wf[i][c][1] = 0ull;
            }
        }
    }

    // ---- init: x_proj coefficients. lane l: row xrow = l>>2, dims 4*(l&3).. ----
    const int xrow = lane >> 2;
    const int xd   = 4 * (lane & 3);
    float4 wih4 = make_float4(0.f, 0.f, 0.f, 0.f);
    float  rbias = 0.f;
    if (rv[xrow]) {
        wih4 = *(const float4*)(Wih + (size_t)gr[xrow] * IN_DIM + xd);
        if ((lane & 3) == 0)
            rbias = __ldg(bih + gr[xrow]) + __ldg(bhh + gr[xrow]);
    }

    // SMEM weight row pointers (lane offset folded in).
    const uint2* wrp[8];
    #pragma unroll
    for (int i = 0; i < 8; ++i)
        wrp[i] = (const uint2*)(wsm + (size_t)rl[i] * W_ROW_B + 8 * lane);

    float c_st = 0.f;     // cell state: lane0 -> unit w, lane1 -> unit w+7
    int   target = 0;
    const unsigned FULL = 0xffffffffu;

    for (int t = 0; t < SEQ; ++t) {
        // ---- x_proj (independent of h — overlaps the barrier wait) ----
        float4 sv = __ldg((const float4*)(sa + (size_t)t * IN_DIM + xd));
        float p = wih4.x * sv.x + wih4.y * sv.y + wih4.z * sv.z + wih4.w * sv.w + rbias;
        p += __shfl_xor_sync(FULL, p, 1);
        p += __shfl_xor_sync(FULL, p, 2);
        float g0 = __shfl_sync(FULL, p, 0),  g1 = __shfl_sync(FULL, p, 4);
        float g2 = __shfl_sync(FULL, p, 8),  g3 = __shfl_sync(FULL, p, 12);
        float g4 = __shfl_sync(FULL, p, 16), g5 = __shfl_sync(FULL, p, 20);
        float g6 = __shfl_sync(FULL, p, 24), g7 = __shfl_sync(FULL, p, 28);

        // ---- single-poller grid barrier ----
        if (tid == 0) { while (ld_acq(&d_cnt) < target) { } }
        __syncthreads();

        // ---- stage h_t into SMEM ----
        {
            const float4* hrow = (const float4*)(d_hs + (size_t)t * HD);
            for (int i = tid; i < HD / 4; i += TPB)
                ((float4*)h_sm)[i] = __ldcg(hrow + i);
        }
        __syncthreads();

        // ---- 8 row dot-products, packed f32x2 ----
        unsigned long long acc[8];
        #pragma unroll
        for (int i = 0; i < 8; ++i) acc[i] = 0ull;
        const ulonglong2* h8 = (const ulonglong2*)h_sm;

        #pragma unroll
        for (int k = 0; k < SCH; ++k) {
            ulonglong2 hv = h8[lane + 32 * k];
            #pragma unroll
            for (int i = 0; i < 8; ++i) {
                uint2 u = wrp[i][32 * k];
                ffma2_bf(acc[i], u.x, hv.x);
                ffma2_bf(acc[i], u.y, hv.y);
            }
        }
        #pragma unroll
        for (int c = 0; c < RCH; ++c) {
            ulonglong2 hv = h8[(SMEM_W_COLS / 4) + 32 * c + lane];
            #pragma unroll
            for (int i = 0; i < 8; ++i) {
                ffma2_f(acc[i], wf[i][c][0], hv.x);
                ffma2_f(acc[i], wf[i][c][1], hv.y);
            }
        }

        float a[8];
        #pragma unroll
        for (int i = 0; i < 8; ++i) {
            unsigned lo, hi;
            asm("mov.b64 {%0,%1}, %2;" : "=r"(lo), "=r"(hi) : "l"(acc[i]));
            a[i] = __uint_as_float(lo) + __uint_as_float(hi);
        }
        #pragma unroll
        for (int m = 16; m >= 1; m >>= 1) {
            #pragma unroll
            for (int i = 0; i < 8; ++i)
                a[i] += __shfl_xor_sync(FULL, a[i], m);
        }

        // ---- elementwise update: lane0 -> unit w, lane1 -> unit w+7 ----
        int u = w + 7 * lane;
        if (lane < 2 && u < J) {
            float ai = lane ? a[4] + g4 : a[0] + g0;
            float af = lane ? a[5] + g5 : a[1] + g1;
            float ag = lane ? a[6] + g6 : a[2] + g2;
            float ao = lane ? a[7] + g7 : a[3] + g3;
            float ig = sigmoidf_(ai);
            float fg = sigmoidf_(af);
            float gg = tanh_fast(ag);
            float og = sigmoidf_(ao);
            c_st = fg * c_st + ig * gg;
            d_hs[(size_t)(t + 1) * HD + j0 + u] = og * tanh_fast(c_st);
        }
        __syncthreads();

        if (tid == 0) {
            __threadfence();            // publish h stores before arrival
            red_rel_add(&d_cnt, 1);
        }
        target += NCTA;
    }
}

// ---------------------------------------------------------------------------
// Final projection: out[t] = [ hs[t]·W_uvw^T + b_uvw , hs[t]·W_pqr^T + b_pqr ]
// One warp per timestep.
// ---------------------------------------------------------------------------
extern "C" __global__ void __launch_bounds__(256)
proj_kernel(const float* __restrict__ Wuvw, const float* __restrict__ buvw,
            const float* __restrict__ Wpqr, const float* __restrict__ bpqr,
            float* __restrict__ out)
{
    int warp = threadIdx.x >> 5, lane = threadIdx.x & 31;
    int t = blockIdx.x * 8 + warp;
    if (t >= SEQ) return;

    const float4* h4 = (const float4*)(d_hs + (size_t)(t + 1) * HD);
    float a0 = 0.f, a1 = 0.f, a2 = 0.f, a3 = 0.f, a4 = 0.f, a5 = 0.f;

    #pragma unroll
    for (int k = 0; k < 16; ++k) {
        float4 hv = h4[lane + 32 * k];
        float4 w0 = __ldg((const float4*)(Wuvw + 0 * HD) + lane + 32 * k);
        float4 w1 = __ldg((const float4*)(Wuvw + 1 * HD) + lane + 32 * k);
        float4 w2 = __ldg((const float4*)(Wuvw + 2 * HD) + lane + 32 * k);
        float4 w3 = __ldg((const float4*)(Wpqr + 0 * HD) + lane + 32 * k);
        float4 w4 = __ldg((const float4*)(Wpqr + 1 * HD) + lane + 32 * k);
        float4 w5 = __ldg((const float4*)(Wpqr + 2 * HD) + lane + 32 * k);
        a0 += hv.x*w0.x + hv.y*w0.y + hv.z*w0.z + hv.w*w0.w;
        a1 += hv.x*w1.x + hv.y*w1.y + hv.z*w1.z + hv.w*w1.w;
        a2 += hv.x*w2.x + hv.y*w2.y + hv.z*w2.z + hv.w*w2.w;
        a3 += hv.x*w3.x + hv.y*w3.y + hv.z*w3.z + hv.w*w3.w;
        a4 += hv.x*w4.x + hv.y*w4.y + hv.z*w4.z + hv.w*w4.w;
        a5 += hv.x*w5.x + hv.y*w5.y + hv.z*w5.z + hv.w*w5.w;
    }
    #pragma unroll
    for (int m = 16; m >= 1; m >>= 1) {
        a0 += __shfl_xor_sync(0xffffffffu, a0, m);
        a1 += __shfl_xor_sync(0xffffffffu, a1, m);
        a2 += __shfl_xor_sync(0xffffffffu, a2, m);
        a3 += __shfl_xor_sync(0xffffffffu, a3, m);
        a4 += __shfl_xor_sync(0xffffffffu, a4, m);
        a5 += __shfl_xor_sync(0xffffffffu, a5, m);
    }
    if (lane == 0) {
        float* o = out + (size_t)t * 6;
        o[0] = a0 + __ldg(buvw + 0);
        o[1] = a1 + __ldg(buvw + 1);
        o[2] = a2 + __ldg(buvw + 2);
        o[3] = a3 + __ldg(bpqr + 0);
        o[4] = a4 + __ldg(bpqr + 1);
        o[5] = a5 + __ldg(bpqr + 2);
    }
}

// Reset h_0 = 0 and d_cnt = 0 (stream-ordered before the persistent kernel).
extern "C" __global__ void reset_kernel()
{
    int i = blockIdx.x * blockDim.x + threadIdx.x;
    if (i < HD) d_hs[i] = 0.0f;
    if (i == 0) d_cnt = 0;
}

extern "C" void kernel_launch(void* const* d_in, const int* in_sizes, int n_in,
                              void* d_out, int out_size)
{
    const float* sa   = (const float*)d_in[0];
    const float* Wih  = (const float*)d_in[1];
    const float* Whh  = (const float*)d_in[2];
    const float* bih  = (const float*)d_in[3];
    const float* bhh  = (const float*)d_in[4];
    const float* Wuvw = (const float*)d_in[5];
    const float* buvw = (const float*)d_in[6];
    const float* Wpqr = (const float*)d_in[7];
    const float* bpqr = (const float*)d_in[8];
    float* out = (float*)d_out;

    cudaFuncSetAttribute(lstm_persist,
                         cudaFuncAttributeMaxDynamicSharedMemorySize, SMEM_BYTES);

    reset_kernel<<<8, 256>>>();
    lstm_persist<<<NCTA, TPB, SMEM_BYTES>>>(sa, Wih, Whh, bih, bhh);
    proj_kernel<<<SEQ / 8, 256>>>(Wuvw, buvw, Wpqr, bpqr, out);
    (void)in_sizes; (void)n_in; (void)out_size;
}

// round 10
// speedup vs baseline: 1.2757x; 1.2757x over previous
#include <cuda_runtime.h>
#include <cuda_bf16.h>
#include <cstdint>
#include <cstddef>

#define HD        2048
#define SEQ       8192
#define IN_DIM    16
#define NCTA      147
#define JCAP      14
#define WARPS     7
#define TPB       (WARPS * 32)        // 224 threads
#define SCH       12                  // smem bf16 weight chunks (cols 0..1535)
#define RCH       4                   // reg fp32 weight chunks (cols 1536..2047)
#define SMEM_W_COLS (SCH * 128)       // 1536
#define W_ROW_B   (SMEM_W_COLS * 2)   // 3072 bytes per bf16 weight row
#define NCHUNK    (NCTA * 5)          // 735 tagged h-exchange chunks
#define SMEM_BYTES (HD * 4 + 256 + 56 * W_ROW_B)   // 180480

// Persistent scratch (static __device__ globals — no allocation APIs).
__device__ float  d_hs[(size_t)(SEQ + 1) * HD];  // h history for projection
__device__ float4 d_hx[2][NCHUNK];               // tagged h exchange, 2 parities

__device__ __forceinline__ float4 ldcg4(const float4* p) {
    float4 v;
    asm volatile("ld.global.cg.v4.f32 {%0,%1,%2,%3}, [%4];"
                 : "=f"(v.x), "=f"(v.y), "=f"(v.z), "=f"(v.w) : "l"(p));
    return v;
}
__device__ __forceinline__ void stcg4(float4* p, float4 v) {
    asm volatile("st.global.cg.v4.f32 [%0], {%1,%2,%3,%4};"
                 :: "l"(p), "f"(v.x), "f"(v.y), "f"(v.z), "f"(v.w) : "memory");
}

__device__ __forceinline__ float sigmoidf_(float x) {
    return 1.0f / (1.0f + __expf(-x));
}
__device__ __forceinline__ float tanh_fast(float x) {
    float xc = fminf(fmaxf(x, -15.0f), 15.0f);
    float a = __expf(2.0f * xc);
    return (a - 1.0f) / (a + 1.0f);
}

// Packed f32x2 FMA: acc(2xf32) += unpack_bf16x2(u) * h2(2xf32)
__device__ __forceinline__ void ffma2_bf(unsigned long long& acc, unsigned u,
                                         unsigned long long h2) {
    unsigned long long wpk;
    asm("{\n\t"
        ".reg .b32 lo, hi;\n\t"
        "shl.b32 lo, %1, 16;\n\t"
        "and.b32 hi, %1, 0xffff0000;\n\t"
        "mov.b64 %0, {lo, hi};\n\t"
        "}" : "=l"(wpk) : "r"(u));
    asm("fma.rn.f32x2 %0, %1, %2, %0;" : "+l"(acc) : "l"(wpk), "l"(h2));
}
__device__ __forceinline__ void ffma2_f(unsigned long long& acc,
                                        unsigned long long wpk,
                                        unsigned long long h2) {
    asm("fma.rn.f32x2 %0, %1, %2, %0;" : "+l"(acc) : "l"(wpk), "l"(h2));
}
__device__ __forceinline__ unsigned long long pack2f(float a, float b) {
    return (unsigned long long)__float_as_uint(a) |
           ((unsigned long long)__float_as_uint(b) << 32);
}

// ---------------------------------------------------------------------------
// Persistent LSTM. CTA b owns hidden units [b*14, b*14+J). 7 warps × 8 gate
// rows. Weights: cols [0,1536) bf16 in SMEM, cols [1536,2048) fp32 pairs in
// registers. h exchange: one-sided tagged 16B chunks (tag rides in .w of the
// same 16B store — no fence, no atomics), double-buffered by step parity.
// Chunk c (in-block index li=c%5) carries min(3, 14-3*li) VALID values; the
// consumer must honor that bound (unit 14b+14 belongs to CTA b+1!).
// ---------------------------------------------------------------------------
extern "C" __global__ void __launch_bounds__(TPB, 1)
lstm_persist(const float* __restrict__ sa,  const float* __restrict__ Wih,
             const float* __restrict__ Whh, const float* __restrict__ bih,
             const float* __restrict__ bhh)
{
    extern __shared__ unsigned char smem[];
    float*         h_sm = (float*)smem;                 // 2048 f32
    float*         gbuf = (float*)(smem + HD * 4);      // 56 f32 gate staging
    unsigned char* wsm  = smem + HD * 4 + 256;          // bf16 weights

    const int tid  = threadIdx.x;
    const int w    = tid >> 5;
    const int lane = tid & 31;
    const int b    = blockIdx.x;
    const int j0   = b * JCAP;
    const int J    = (b == NCTA - 1) ? (HD - (NCTA - 1) * JCAP) : JCAP;  // 14 or 4

    // Row set: i = 0..7 -> gate g = i&3 of unit jj = w + 7*(i>>2).
    int  rl[8], gr[8];
    bool rv[8];
    #pragma unroll
    for (int i = 0; i < 8; ++i) {
        int jj = w + 7 * (i >> 2);
        int g  = i & 3;
        rv[i] = (jj < J);
        int jjc = rv[i] ? jj : 0;
        rl[i] = g * J + jjc;
        gr[i] = g * HD + j0 + jjc;
    }

    // ---- init: stage bf16 weights for cols [0,1536) into SMEM ----
    for (int idx = tid; idx < 4 * J * SMEM_W_COLS; idx += TPB) {
        int r   = idx / SMEM_W_COLS;
        int col = idx - r * SMEM_W_COLS;
        int gg  = r / J, jj = r - gg * J;
        int grow = gg * HD + j0 + jj;
        ((__nv_bfloat16*)wsm)[(size_t)r * SMEM_W_COLS + col] =
            __float2bfloat16(Whh[(size_t)grow * HD + col]);
    }

    // ---- init: fp32 register weights for cols [1536,2048), packed pairs ----
    unsigned long long wf[8][RCH][2];
    #pragma unroll
    for (int i = 0; i < 8; ++i) {
        #pragma unroll
        for (int c = 0; c < RCH; ++c) {
            if (rv[i]) {
                const float* wr = Whh + (size_t)gr[i] * HD + SMEM_W_COLS + 128 * c + 4 * lane;
                wf[i][c][0] = pack2f(wr[0], wr[1]);
                wf[i][c][1] = pack2f(wr[2], wr[3]);
            } else {
                wf[i][c][0] = 0ull; wf[i][c][1] = 0ull;
            }
        }
    }

    // ---- init: x_proj coefficients: lane l -> row l>>2, dims 4*(l&3) ----
    const int xrow = lane >> 2;
    const int xd   = 4 * (lane & 3);
    float4 wih4 = make_float4(0.f, 0.f, 0.f, 0.f);
    float  rbias = 0.f;
    if (rv[xrow]) {
        wih4 = *(const float4*)(Wih + (size_t)gr[xrow] * IN_DIM + xd);
        if ((lane & 3) == 0)
            rbias = __ldg(bih + gr[xrow]) + __ldg(bhh + gr[xrow]);
    }

    // SMEM weight row pointers.
    const uint2* wrp[8];
    #pragma unroll
    for (int i = 0; i < 8; ++i)
        wrp[i] = (const uint2*)(wsm + (size_t)rl[i] * W_ROW_B + 8 * lane);

    // Consumer chunk assignment (3 or 4 chunks per thread) + per-chunk
    // valid-count (FIX for R9: chunk li=4 carries only 2 valid values).
    int cch[4], cbase[4], cnum[4], nch = 0;
    for (int c = tid; c < NCHUNK; c += TPB) {
        int b5 = c / 5, li = c - 5 * b5;
        int base = b5 * JCAP + 3 * li;
        int nv = JCAP - 3 * li; if (nv > 3) nv = 3;
        if (base + nv > HD) nv = HD - base;          // last CTA tail
        if (nv < 0) nv = 0;
        cch[nch] = c; cbase[nch] = base; cnum[nch] = nv;
        ++nch;
    }

    float c_st = 0.f;     // cell state: warp 0 lane u -> unit u
    const unsigned FULL = 0xffffffffu;

    for (int t = 0; t < SEQ; ++t) {
        // ---- x_proj (independent of h): overlaps the chunk wait ----
        float4 sv = __ldg((const float4*)(sa + (size_t)t * IN_DIM + xd));
        float p = wih4.x * sv.x + wih4.y * sv.y + wih4.z * sv.z + wih4.w * sv.w + rbias;
        p += __shfl_xor_sync(FULL, p, 1);
        p += __shfl_xor_sync(FULL, p, 2);
        float g0 = __shfl_sync(FULL, p, 0),  g1 = __shfl_sync(FULL, p, 4);
        float g2 = __shfl_sync(FULL, p, 8),  g3 = __shfl_sync(FULL, p, 12);
        float g4 = __shfl_sync(FULL, p, 16), g5 = __shfl_sync(FULL, p, 20);
        float g6 = __shfl_sync(FULL, p, 24), g7 = __shfl_sync(FULL, p, 28);

        // ---- consume tagged h chunks for step t (parity t&1) ----
        {
            const float4* hx = d_hx[t & 1];
            float4 v[4];
            #pragma unroll
            for (int i = 0; i < 4; ++i)
                if (i < nch) v[i] = ldcg4(hx + cch[i]);
            bool done = false;
            while (!done) {
                done = true;
                #pragma unroll
                for (int i = 0; i < 4; ++i) {
                    if (i < nch && __float_as_int(v[i].w) != t) {
                        v[i] = ldcg4(hx + cch[i]);
                        done = false;
                    }
                }
            }
            #pragma unroll
            for (int i = 0; i < 4; ++i) {
                if (i < nch) {
                    int base = cbase[i], nv = cnum[i];
                    if (nv > 0) h_sm[base + 0] = v[i].x;
                    if (nv > 1) h_sm[base + 1] = v[i].y;
                    if (nv > 2) h_sm[base + 2] = v[i].z;
                }
            }
        }
        __syncthreads();

        // ---- 8 row dot-products, packed f32x2 ----
        unsigned long long acc[8];
        #pragma unroll
        for (int i = 0; i < 8; ++i) acc[i] = 0ull;
        const ulonglong2* h8 = (const ulonglong2*)h_sm;

        #pragma unroll
        for (int k = 0; k < SCH; ++k) {
            ulonglong2 hv = h8[lane + 32 * k];
            #pragma unroll
            for (int i = 0; i < 8; ++i) {
                uint2 u = wrp[i][32 * k];
                ffma2_bf(acc[i], u.x, hv.x);
                ffma2_bf(acc[i], u.y, hv.y);
            }
        }
        #pragma unroll
        for (int c = 0; c < RCH; ++c) {
            ulonglong2 hv = h8[(SMEM_W_COLS / 4) + 32 * c + lane];
            #pragma unroll
            for (int i = 0; i < 8; ++i) {
                ffma2_f(acc[i], wf[i][c][0], hv.x);
                ffma2_f(acc[i], wf[i][c][1], hv.y);
            }
        }

        float a[8];
        #pragma unroll
        for (int i = 0; i < 8; ++i) {
            unsigned lo, hi;
            asm("mov.b64 {%0,%1}, %2;" : "=r"(lo), "=r"(hi) : "l"(acc[i]));
            a[i] = __uint_as_float(lo) + __uint_as_float(hi);
        }
        #pragma unroll
        for (int m = 16; m >= 1; m >>= 1) {
            #pragma unroll
            for (int i = 0; i < 8; ++i)
                a[i] += __shfl_xor_sync(FULL, a[i], m);
        }

        if (lane == 0) {
            // rows: i -> gate (i&3), unit (w + 7*(i>>2)); gbuf gate-major [4][14]
            gbuf[0 * JCAP + w    ] = a[0] + g0;
            gbuf[1 * JCAP + w    ] = a[1] + g1;
            gbuf[2 * JCAP + w    ] = a[2] + g2;
            gbuf[3 * JCAP + w    ] = a[3] + g3;
            gbuf[0 * JCAP + w + 7] = a[4] + g4;
            gbuf[1 * JCAP + w + 7] = a[5] + g5;
            gbuf[2 * JCAP + w + 7] = a[6] + g6;
            gbuf[3 * JCAP + w + 7] = a[7] + g7;
        }
        __syncthreads();

        // ---- warp 0: elementwise + publish tagged chunks ----
        if (w == 0) {
            float hval = 0.f;
            if (lane < JCAP) {
                float ai = gbuf[lane];
                float af = gbuf[JCAP + lane];
                float ag = gbuf[2 * JCAP + lane];
                float ao = gbuf[3 * JCAP + lane];
                float ig = sigmoidf_(ai);
                float fg = sigmoidf_(af);
                float gg = tanh_fast(ag);
                float og = sigmoidf_(ao);
                c_st = fg * c_st + ig * gg;
                float hv_ = og * tanh_fast(c_st);
                if (lane < J) {
                    hval = hv_;
                    d_hs[(size_t)(t + 1) * HD + j0 + lane] = hval;  // for proj
                }
            }
            // gather triples and publish (lanes 0..4); consumer ignores the
            // out-of-block 15th slot (lane 14's zero) via cnum guard.
            int s0 = 3 * lane, s1 = 3 * lane + 1, s2 = 3 * lane + 2;
            float h0 = __shfl_sync(FULL, hval, s0 & 31);
            float h1 = __shfl_sync(FULL, hval, s1 & 31);
            float h2 = __shfl_sync(FULL, hval, s2 & 31);
            if (lane < 5) {
                float4 chunk = make_float4(h0, h1, h2, __int_as_float(t + 1));
                stcg4(&d_hx[(t + 1) & 1][b * 5 + lane], chunk);
            }
        }
        // no trailing barrier: scatter for t+1 happens after sync #2, when
        // every warp has finished reading h_sm for step t.
    }
}

// ---------------------------------------------------------------------------
// Final projection: out[t] = [ hs[t]·W_uvw^T + b_uvw , hs[t]·W_pqr^T + b_pqr ]
// ---------------------------------------------------------------------------
extern "C" __global__ void __launch_bounds__(256)
proj_kernel(const float* __restrict__ Wuvw, const float* __restrict__ buvw,
            const float* __restrict__ Wpqr, const float* __restrict__ bpqr,
            float* __restrict__ out)
{
    int warp = threadIdx.x >> 5, lane = threadIdx.x & 31;
    int t = blockIdx.x * 8 + warp;
    if (t >= SEQ) return;

    const float4* h4 = (const float4*)(d_hs + (size_t)(t + 1) * HD);
    float a0 = 0.f, a1 = 0.f, a2 = 0.f, a3 = 0.f, a4 = 0.f, a5 = 0.f;

    #pragma unroll
    for (int k = 0; k < 16; ++k) {
        float4 hv = h4[lane + 32 * k];
        float4 w0 = __ldg((const float4*)(Wuvw + 0 * HD) + lane + 32 * k);
        float4 w1 = __ldg((const float4*)(Wuvw + 1 * HD) + lane + 32 * k);
        float4 w2 = __ldg((const float4*)(Wuvw + 2 * HD) + lane + 32 * k);
        float4 w3 = __ldg((const float4*)(Wpqr + 0 * HD) + lane + 32 * k);
        float4 w4 = __ldg((const float4*)(Wpqr + 1 * HD) + lane + 32 * k);
        float4 w5 = __ldg((const float4*)(Wpqr + 2 * HD) + lane + 32 * k);
        a0 += hv.x*w0.x + hv.y*w0.y + hv.z*w0.z + hv.w*w0.w;
        a1 += hv.x*w1.x + hv.y*w1.y + hv.z*w1.z + hv.w*w1.w;
        a2 += hv.x*w2.x + hv.y*w2.y + hv.z*w2.z + hv.w*w2.w;
        a3 += hv.x*w3.x + hv.y*w3.y + hv.z*w3.z + hv.w*w3.w;
        a4 += hv.x*w4.x + hv.y*w4.y + hv.z*w4.z + hv.w*w4.w;
        a5 += hv.x*w5.x + hv.y*w5.y + hv.z*w5.z + hv.w*w5.w;
    }
    #pragma unroll
    for (int m = 16; m >= 1; m >>= 1) {
        a0 += __shfl_xor_sync(0xffffffffu, a0, m);
        a1 += __shfl_xor_sync(0xffffffffu, a1, m);
        a2 += __shfl_xor_sync(0xffffffffu, a2, m);
        a3 += __shfl_xor_sync(0xffffffffu, a3, m);
        a4 += __shfl_xor_sync(0xffffffffu, a4, m);
        a5 += __shfl_xor_sync(0xffffffffu, a5, m);
    }
    if (lane == 0) {
        float* o = out + (size_t)t * 6;
        o[0] = a0 + __ldg(buvw + 0);
        o[1] = a1 + __ldg(buvw + 1);
        o[2] = a2 + __ldg(buvw + 2);
        o[3] = a3 + __ldg(bpqr + 0);
        o[4] = a4 + __ldg(bpqr + 1);
        o[5] = a5 + __ldg(bpqr + 2);
    }
}

// Reset the tagged exchange buffers (tags+data -> 0) each replay.
extern "C" __global__ void reset_kernel()
{
    int i = blockIdx.x * blockDim.x + threadIdx.x;
    if (i < 2 * NCHUNK)
        ((float4*)d_hx)[i] = make_float4(0.f, 0.f, 0.f, 0.f);
}

extern "C" void kernel_launch(void* const* d_in, const int* in_sizes, int n_in,
                              void* d_out, int out_size)
{
    const float* sa   = (const float*)d_in[0];
    const float* Wih  = (const float*)d_in[1];
    const float* Whh  = (const float*)d_in[2];
    const float* bih  = (const float*)d_in[3];
    const float* bhh  = (const float*)d_in[4];
    const float* Wuvw = (const float*)d_in[5];
    const float* buvw = (const float*)d_in[6];
    const float* Wpqr = (const float*)d_in[7];
    const float* bpqr = (const float*)d_in[8];
    float* out = (float*)d_out;

    cudaFuncSetAttribute(lstm_persist,
                         cudaFuncAttributeMaxDynamicSharedMemorySize, SMEM_BYTES);

    reset_kernel<<<8, 256>>>();
    lstm_persist<<<NCTA, TPB, SMEM_BYTES>>>(sa, Wih, Whh, bih, bhh);
    proj_kernel<<<SEQ / 8, 256>>>(Wuvw, buvw, Wpqr, bpqr, out);
    (void)in_sizes; (void)n_in; (void)out_size;
}